// round 16
// baseline (speedup 1.0000x reference)
#include <cuda_runtime.h>
#include <cstdint>

#define B_   4
#define T_   2048
#define HIN_ 1024
#define H_   16
#define E_   64
#define HE_  (H_ * E_)   // 1024
#define BT_  (B_ * T_)   // 8192
#define NSPLIT 2
#define TSPLIT (T_ / NSPLIT)   // 1024 keys per split

// Persistent scratch (no allocations allowed in kernel_launch).
__device__ float g_Q[BT_ * HE_];
__device__ float g_K[BT_ * HE_];
__device__ float g_V[BT_ * HE_];
__device__ float g_Op[NSPLIT * BT_ * HE_];   // unnormalized partial O
__device__ float g_m[NSPLIT * BT_ * H_];     // running max per row
__device__ float g_l[NSPLIT * BT_ * H_];     // running sum per row

// ---------------------------------------------------------------------------
// Packed fp32x2 helpers (Blackwell FFMA2 via PTX f32x2)
// ---------------------------------------------------------------------------
typedef unsigned long long u64;

__device__ __forceinline__ u64 pack2(float lo, float hi) {
    u64 r;
    asm("mov.b64 %0, {%1,%2};" : "=l"(r) : "f"(lo), "f"(hi));
    return r;
}
__device__ __forceinline__ float2 unpack2(u64 v) {
    float2 r;
    asm("mov.b64 {%0,%1}, %2;" : "=f"(r.x), "=f"(r.y) : "l"(v));
    return r;
}
__device__ __forceinline__ void fma2(u64& d, u64 a, u64 b) {
    asm("fma.rn.f32x2 %0, %1, %2, %0;" : "+l"(d) : "l"(a), "l"(b));
}
__device__ __forceinline__ u64 mul2(u64 a, u64 b) {
    u64 r;
    asm("mul.rn.f32x2 %0, %1, %2;" : "=l"(r) : "l"(a), "l"(b));
    return r;
}

// ---------------------------------------------------------------------------
// Projection GEMM, KV-fused (z=0: Q; z=1: K+V share the A tile) — unchanged.
// ---------------------------------------------------------------------------
__global__ __launch_bounds__(128) void proj_gemm(const float* __restrict__ Aq,
                                                 const float* __restrict__ Akv,
                                                 const float* __restrict__ Wq,
                                                 const float* __restrict__ Wk,
                                                 const float* __restrict__ Wv,
                                                 float scale) {
    __shared__ __align__(16) float AsT[2][16][64];      // [buf][k][m-swizzled]
    __shared__ __align__(16) float Ws[2][2][16][68];    // [buf][mat][k][n]

    const int fused = blockIdx.z;         // 0: Q, 1: K+V
    const float* __restrict__ A  = fused ? Akv : Aq;
    const float* __restrict__ W0 = fused ? Wk : Wq;
    const float* __restrict__ W1 = Wv;    // used only when fused
    float* __restrict__ C0 = fused ? g_K : g_Q;
    float* __restrict__ C1 = g_V;

    const int tid = threadIdx.x;
    const int ty = tid >> 4;          // 0..7  (8 rows each)
    const int tx = tid & 15;          // 0..15 (4 cols each)
    const int bm = blockIdx.y << 6;
    const int bn = blockIdx.x << 6;

    const int ar = tid >> 1;
    const int ac = (tid & 1) << 3;
    const int wr = tid >> 3;
    const int wc = (tid & 7) << 3;

    const float* Ap  = A + (size_t)(bm + ar) * HIN_ + ac;
    const float* W0p = W0 + (size_t)wr * HE_ + bn + wc;
    const float* W1p = W1 + (size_t)wr * HE_ + bn + wc;

    u64 acc0[8][2], acc1[8][2];
#pragma unroll
    for (int i = 0; i < 8; i++) {
        acc0[i][0] = 0ull; acc0[i][1] = 0ull;
        acc1[i][0] = 0ull; acc1[i][1] = 0ull;
    }

    // swizzle: storage col of (k, m) = m ^ (((k>>2)&3)<<2)
    {   // prologue: chunk 0
        float4 a0 = *(const float4*)(Ap);
        float4 a1 = *(const float4*)(Ap + 4);
        float av[8] = {a0.x, a0.y, a0.z, a0.w, a1.x, a1.y, a1.z, a1.w};
#pragma unroll
        for (int j = 0; j < 8; j++) {
            int k = ac + j;
            AsT[0][k][ar ^ (((k >> 2) & 3) << 2)] = av[j];
        }
        *(float4*)&Ws[0][0][wr][wc]     = *(const float4*)(W0p);
        *(float4*)&Ws[0][0][wr][wc + 4] = *(const float4*)(W0p + 4);
        if (fused) {
            *(float4*)&Ws[0][1][wr][wc]     = *(const float4*)(W1p);
            *(float4*)&Ws[0][1][wr][wc + 4] = *(const float4*)(W1p + 4);
        }
    }
    __syncthreads();

    int buf = 0;
    for (int it = 1; it <= 64; it++) {
        float4 a0, a1, wa0, wa1, wb0, wb1;
        if (it < 64) {   // prefetch chunk it
            a0 = *(const float4*)(Ap + it * 16);
            a1 = *(const float4*)(Ap + it * 16 + 4);
            wa0 = *(const float4*)(W0p + (size_t)it * 16 * HE_);
            wa1 = *(const float4*)(W0p + (size_t)it * 16 * HE_ + 4);
            if (fused) {
                wb0 = *(const float4*)(W1p + (size_t)it * 16 * HE_);
                wb1 = *(const float4*)(W1p + (size_t)it * 16 * HE_ + 4);
            }
        }

        // compute chunk it-1 from buf
#pragma unroll
        for (int kk = 0; kk < 16; kk++) {
            int cx = ((kk >> 2) & 3) << 2;
            float4 aa0 = *(const float4*)&AsT[buf][kk][(ty << 3) ^ cx];
            float4 aa1 = *(const float4*)&AsT[buf][kk][((ty << 3) + 4) ^ cx];
            ulonglong2 w2 =
                *(const ulonglong2*)&Ws[buf][0][kk][tx << 2];  // packed span
            float a[8] = {aa0.x, aa0.y, aa0.z, aa0.w,
                          aa1.x, aa1.y, aa1.z, aa1.w};
#pragma unroll
            for (int i = 0; i < 8; i++) {
                u64 ad = pack2(a[i], a[i]);
                fma2(acc0[i][0], ad, w2.x);
                fma2(acc0[i][1], ad, w2.y);
            }
            if (fused) {
                ulonglong2 v2 =
                    *(const ulonglong2*)&Ws[buf][1][kk][tx << 2];
#pragma unroll
                for (int i = 0; i < 8; i++) {
                    u64 ad = pack2(a[i], a[i]);
                    fma2(acc1[i][0], ad, v2.x);
                    fma2(acc1[i][1], ad, v2.y);
                }
            }
        }

        if (it < 64) {
            int nb = buf ^ 1;
            float av[8] = {a0.x, a0.y, a0.z, a0.w, a1.x, a1.y, a1.z, a1.w};
#pragma unroll
            for (int j = 0; j < 8; j++) {
                int k = ac + j;
                AsT[nb][k][ar ^ (((k >> 2) & 3) << 2)] = av[j];
            }
            *(float4*)&Ws[nb][0][wr][wc]     = wa0;
            *(float4*)&Ws[nb][0][wr][wc + 4] = wa1;
            if (fused) {
                *(float4*)&Ws[nb][1][wr][wc]     = wb0;
                *(float4*)&Ws[nb][1][wr][wc + 4] = wb1;
            }
            __syncthreads();
            buf = nb;
        }
    }

    // Epilogue: Q and K carry the softmax scale; V is unscaled.
#pragma unroll
    for (int i = 0; i < 8; i++) {
        float2 p0 = unpack2(acc0[i][0]);
        float2 p1 = unpack2(acc0[i][1]);
        float4 r = make_float4(p0.x * scale, p0.y * scale,
                               p1.x * scale, p1.y * scale);
        *(float4*)&C0[(size_t)(bm + (ty << 3) + i) * HE_ + bn + (tx << 2)] = r;
    }
    if (fused) {
#pragma unroll
        for (int i = 0; i < 8; i++) {
            float2 p0 = unpack2(acc1[i][0]);
            float2 p1 = unpack2(acc1[i][1]);
            float4 r = make_float4(p0.x, p0.y, p1.x, p1.y);
            *(float4*)&C1[(size_t)(bm + (ty << 3) + i) * HE_ + bn + (tx << 2)] = r;
        }
    }
}

// ---------------------------------------------------------------------------
// Flash attention, split-K. R16: row-PAIR-packed accumulators.
//  - QK: q row-pairs read directly as u64 from QsT (contiguous, free);
//        only K is broadcast-packed (4 packs/e-step instead of 8).
//  - PV: P stored TRANSPOSED as u64 row-pairs (PsT aliases KsT storage,
//        XOR-swizzled by (k>>2)&7); P pairs are free LDS.128 broadcasts;
//        only V is broadcast-packed (4 packs/k instead of 8).
// All products land in the same accumulator in the same order -> bit-identical.
// ---------------------------------------------------------------------------
__global__ __launch_bounds__(128) void flash_attn_split() {
    __shared__ __align__(16) float QsT[64][64];  // swizzled [e][qrow]
    __shared__ __align__(16) float KsT[64][64];  // swizzled [e][krow]; P_T reuse
    __shared__ __align__(16) float Vs[64][64];   // [krow][e]

    u64 (*PsT)[32] = (u64(*)[32])KsT;            // P_T[k][rowpair] alias

    const int tid = threadIdx.x;
    const int ty = tid >> 4;        // q-row group 0..7 (8 rows each)
    const int tx = tid & 15;        // col group 0..15 (4 cols each)
    const int q0 = blockIdx.x << 6;
    const int h  = blockIdx.y;
    const int b  = blockIdx.z >> 1;
    const int sp = blockIdx.z & 1;

    const size_t baseQ  = ((size_t)(b * T_ + q0) * H_ + h) * E_;
    const size_t baseKV = ((size_t)(b * T_ + sp * TSPLIT) * H_ + h) * E_;

    for (int idx = tid; idx < 1024; idx += 128) {
        int row = idx >> 4;
        int t = idx & 15;
        int c = t << 2;
        float4 v = *(const float4*)(g_Q + baseQ + (size_t)row * HE_ + c);
        int col = (((row >> 2) ^ t) << 2) | (row & 3);
        QsT[c + 0][col] = v.x;
        QsT[c + 1][col] = v.y;
        QsT[c + 2][col] = v.z;
        QsT[c + 3][col] = v.w;
    }

    float m[8], l[8];
    u64 o2[4][4];   // [rowpair][vcol]
#pragma unroll
    for (int i = 0; i < 8; i++) { m[i] = -1e30f; l[i] = 0.f; }
#pragma unroll
    for (int p = 0; p < 4; p++)
#pragma unroll
        for (int c = 0; c < 4; c++) o2[p][c] = 0ull;

    for (int k0 = 0; k0 < TSPLIT; k0 += 64) {
        __syncthreads();   // prev tile fully consumed (incl. P_T reads)
        for (int idx = tid; idx < 1024; idx += 128) {
            int row = idx >> 4;
            int t = idx & 15;
            int c = t << 2;
            size_t g = baseKV + (size_t)(k0 + row) * HE_ + c;
            float4 kv = *(const float4*)(g_K + g);
            int col = (((row >> 2) ^ t) << 2) | (row & 3);
            KsT[c + 0][col] = kv.x;
            KsT[c + 1][col] = kv.y;
            KsT[c + 2][col] = kv.z;
            KsT[c + 3][col] = kv.w;
            *(float4*)&Vs[row][c] = *(const float4*)(g_V + g);
        }
        __syncthreads();

        // S = Q K^T: row-pair-packed accumulators; K is the broadcast side
        u64 s2[4][4];
#pragma unroll
        for (int p = 0; p < 4; p++)
#pragma unroll
            for (int j = 0; j < 4; j++) s2[p][j] = 0ull;
#pragma unroll 4
        for (int x = 0; x < 16; x++) {
#pragma unroll
            for (int ee = 0; ee < 4; ee++) {
                int e = (x << 2) + ee;
                ulonglong2 qa =
                    *(const ulonglong2*)&QsT[e][((2 * ty) ^ x) << 2];
                ulonglong2 qb =
                    *(const ulonglong2*)&QsT[e][((2 * ty + 1) ^ x) << 2];
                float4 k4 = *(const float4*)&KsT[e][(tx ^ x) << 2];
                u64 kd0 = pack2(k4.x, k4.x);
                u64 kd1 = pack2(k4.y, k4.y);
                u64 kd2 = pack2(k4.z, k4.z);
                u64 kd3 = pack2(k4.w, k4.w);
                u64 q64[4] = {qa.x, qa.y, qb.x, qb.y};
#pragma unroll
                for (int p = 0; p < 4; p++) {
                    fma2(s2[p][0], q64[p], kd0);
                    fma2(s2[p][1], q64[p], kd1);
                    fma2(s2[p][2], q64[p], kd2);
                    fma2(s2[p][3], q64[p], kd3);
                }
            }
        }

        // Unpack to per-row s and run online softmax (pairwise o2 rescale)
        float s[8][4];
#pragma unroll
        for (int p = 0; p < 4; p++)
#pragma unroll
            for (int j = 0; j < 4; j++) {
                float2 t2 = unpack2(s2[p][j]);
                s[2 * p][j] = t2.x;
                s[2 * p + 1][j] = t2.y;
            }
#pragma unroll
        for (int p = 0; p < 4; p++) {
            float corr2[2];
#pragma unroll
            for (int z = 0; z < 2; z++) {
                int i = 2 * p + z;
                float mx = fmaxf(fmaxf(s[i][0], s[i][1]),
                                 fmaxf(s[i][2], s[i][3]));
#pragma unroll
                for (int off = 8; off >= 1; off >>= 1)
                    mx = fmaxf(mx, __shfl_xor_sync(0xffffffffu, mx, off));
                float mnew = fmaxf(m[i], mx);
                float corr = __expf(m[i] - mnew);
                float rs = 0.f;
#pragma unroll
                for (int j = 0; j < 4; j++) {
                    s[i][j] = __expf(s[i][j] - mnew);
                    rs += s[i][j];
                }
#pragma unroll
                for (int off = 8; off >= 1; off >>= 1)
                    rs += __shfl_xor_sync(0xffffffffu, rs, off);
                l[i] = l[i] * corr + rs;
                m[i] = mnew;
                corr2[z] = corr;
            }
            u64 cd = pack2(corr2[0], corr2[1]);
#pragma unroll
            for (int c = 0; c < 4; c++) o2[p][c] = mul2(o2[p][c], cd);
        }

        __syncthreads();   // all warps done reading KsT as K (cross-warp)

        // Store P transposed as row-pair u64s, swizzled by (k>>2)&7 = tx&7
        {
            int swz = ty ^ (tx & 7);
#pragma unroll
            for (int j = 0; j < 4; j++) {
                int k = 4 * tx + j;
                u64 pr0 = pack2(s[0][j], s[1][j]);
                u64 pr1 = pack2(s[2][j], s[3][j]);
                u64 pr2 = pack2(s[4][j], s[5][j]);
                u64 pr3 = pack2(s[6][j], s[7][j]);
                ulonglong2 w0; w0.x = pr0; w0.y = pr1;
                ulonglong2 w1; w1.x = pr2; w1.y = pr3;
                *(ulonglong2*)&PsT[k][4 * swz] = w0;
                *(ulonglong2*)&PsT[k][4 * swz + 2] = w1;
            }
        }
        __syncwarp();      // P_T exchange is warp-internal (same ty group)

        // O += P @ V : P pairs free; V is the broadcast side
#pragma unroll 4
        for (int k = 0; k < 64; k++) {
            int swz = ty ^ ((k >> 2) & 7);
            float4 v4 = *(const float4*)&Vs[k][tx << 2];
            u64 vd0 = pack2(v4.x, v4.x);
            u64 vd1 = pack2(v4.y, v4.y);
            u64 vd2 = pack2(v4.z, v4.z);
            u64 vd3 = pack2(v4.w, v4.w);
            ulonglong2 pa = *(const ulonglong2*)&PsT[k][4 * swz];
            ulonglong2 pb = *(const ulonglong2*)&PsT[k][4 * swz + 2];
            u64 pd[4] = {pa.x, pa.y, pb.x, pb.y};
#pragma unroll
            for (int p = 0; p < 4; p++) {
                fma2(o2[p][0], pd[p], vd0);
                fma2(o2[p][1], pd[p], vd1);
                fma2(o2[p][2], pd[p], vd2);
                fma2(o2[p][3], pd[p], vd3);
            }
        }
    }

    // Write unnormalized partials + (m, l)
    const size_t opBase = (size_t)sp * BT_ * HE_;
    const size_t mlBase = (size_t)sp * BT_ * H_;
#pragma unroll
    for (int p = 0; p < 4; p++) {
        float2 t0 = unpack2(o2[p][0]);
        float2 t1 = unpack2(o2[p][1]);
        float2 t2 = unpack2(o2[p][2]);
        float2 t3 = unpack2(o2[p][3]);
        int row0 = q0 + (ty << 3) + 2 * p;
        *(float4*)&g_Op[opBase + ((size_t)(b * T_ + row0) * H_ + h) * E_ +
                        (tx << 2)] = make_float4(t0.x, t1.x, t2.x, t3.x);
        *(float4*)&g_Op[opBase + ((size_t)(b * T_ + row0 + 1) * H_ + h) * E_ +
                        (tx << 2)] = make_float4(t0.y, t1.y, t2.y, t3.y);
    }
    if (tx == 0) {
#pragma unroll
        for (int i = 0; i < 8; i++) {
            int row = q0 + (ty << 3) + i;
            size_t mi = mlBase + (size_t)(b * T_ + row) * H_ + h;
            g_m[mi] = m[i];
            g_l[mi] = l[i];
        }
    }
}

// ---------------------------------------------------------------------------
// Combine (unchanged).
// ---------------------------------------------------------------------------
__global__ __launch_bounds__(256) void flash_combine(float* __restrict__ Out) {
    int idx = blockIdx.x * 256 + threadIdx.x;   // float4 index
    int rowh = idx >> 4;                         // (b*T+t)*H + h
    float m0 = g_m[rowh];
    float m1 = g_m[BT_ * H_ + rowh];
    float l0 = g_l[rowh];
    float l1 = g_l[BT_ * H_ + rowh];
    float M = fmaxf(m0, m1);
    float w0 = __expf(m0 - M);
    float w1 = __expf(m1 - M);
    float inv = 1.0f / (l0 * w0 + l1 * w1);

    const float4* Op4 = (const float4*)g_Op;
    float4 o0 = Op4[idx];
    float4 o1 = Op4[(BT_ * HE_ / 4) + idx];
    float4 r;
    r.x = (o0.x * w0 + o1.x * w1) * inv;
    r.y = (o0.y * w0 + o1.y * w1) * inv;
    r.z = (o0.z * w0 + o1.z * w1) * inv;
    r.w = (o0.w * w0 + o1.w * w1) * inv;
    ((float4*)Out)[idx] = r;
}

// ---------------------------------------------------------------------------
extern "C" void kernel_launch(void* const* d_in, const int* in_sizes, int n_in,
                              void* d_out, int out_size) {
    const float* query     = (const float*)d_in[0];
    const float* key_value = (const float*)d_in[1];
    const float* Wq        = (const float*)d_in[2];
    const float* Wk        = (const float*)d_in[3];
    const float* Wv        = (const float*)d_in[4];
    float* out = (float*)d_out;

    const float scale = 0.35355339059327379f;  // 64^(-1/4)

    dim3 gproj(HE_ / 64, BT_ / 64, 2);         // (16, 128, 2): z0=Q, z1=K+V
    proj_gemm<<<gproj, 128>>>(query, key_value, Wq, Wk, Wv, scale);

    dim3 gattn(T_ / 64, H_, B_ * NSPLIT);      // (32, 16, 8)
    flash_attn_split<<<gattn, 128>>>();

    flash_combine<<<BT_ * HE_ / 4 / 256, 256>>>(out);
}

// round 17
// speedup vs baseline: 1.0948x; 1.0948x over previous
#include <cuda_runtime.h>
#include <cstdint>

#define B_   4
#define T_   2048
#define HIN_ 1024
#define H_   16
#define E_   64
#define HE_  (H_ * E_)   // 1024
#define BT_  (B_ * T_)   // 8192
#define NSPLIT 2
#define TSPLIT (T_ / NSPLIT)   // 1024 keys per split

// Persistent scratch (no allocations allowed in kernel_launch).
__device__ float g_Q[BT_ * HE_];
__device__ float g_K[BT_ * HE_];
__device__ float g_V[BT_ * HE_];
__device__ float g_Op[NSPLIT * BT_ * HE_];   // unnormalized partial O
__device__ float g_m[NSPLIT * BT_ * H_];     // running max per row
__device__ float g_l[NSPLIT * BT_ * H_];     // running sum per row

// ---------------------------------------------------------------------------
// Packed fp32x2 helpers (Blackwell FFMA2 via PTX f32x2) + cp.async
// ---------------------------------------------------------------------------
typedef unsigned long long u64;

__device__ __forceinline__ u64 pack2(float lo, float hi) {
    u64 r;
    asm("mov.b64 %0, {%1,%2};" : "=l"(r) : "f"(lo), "f"(hi));
    return r;
}
__device__ __forceinline__ float2 unpack2(u64 v) {
    float2 r;
    asm("mov.b64 {%0,%1}, %2;" : "=f"(r.x), "=f"(r.y) : "l"(v));
    return r;
}
__device__ __forceinline__ void fma2(u64& d, u64 a, u64 b) {
    asm("fma.rn.f32x2 %0, %1, %2, %0;" : "+l"(d) : "l"(a), "l"(b));
}
__device__ __forceinline__ u64 mul2(u64 a, u64 b) {
    u64 r;
    asm("mul.rn.f32x2 %0, %1, %2;" : "=l"(r) : "l"(a), "l"(b));
    return r;
}
__device__ __forceinline__ uint32_t smem_u32(const void* p) {
    uint32_t a;
    asm("{ .reg .u64 t; cvta.to.shared.u64 t, %1; cvt.u32.u64 %0, t; }"
        : "=r"(a) : "l"(p));
    return a;
}
#define CP_ASYNC16(dst_u32, src_ptr)                                          \
    asm volatile("cp.async.ca.shared.global [%0], [%1], 16;"                  \
                 :: "r"(dst_u32), "l"(src_ptr) : "memory")
#define CP_COMMIT()  asm volatile("cp.async.commit_group;" ::: "memory")
#define CP_WAIT0()   asm volatile("cp.async.wait_group 0;" ::: "memory")

// ---------------------------------------------------------------------------
// Projection GEMM, KV-fused (z=0: Q; z=1: K+V share the A tile).
// R17: W tiles stream global->smem via cp.async (no W prefetch registers,
// shorter latency chain). A keeps register prefetch (needs transpose+swizzle).
// ---------------------------------------------------------------------------
__global__ __launch_bounds__(128) void proj_gemm(const float* __restrict__ Aq,
                                                 const float* __restrict__ Akv,
                                                 const float* __restrict__ Wq,
                                                 const float* __restrict__ Wk,
                                                 const float* __restrict__ Wv,
                                                 float scale) {
    __shared__ __align__(16) float AsT[2][16][64];      // [buf][k][m-swizzled]
    __shared__ __align__(16) float Ws[2][2][16][68];    // [buf][mat][k][n]

    const int fused = blockIdx.z;         // 0: Q, 1: K+V
    const float* __restrict__ A  = fused ? Akv : Aq;
    const float* __restrict__ W0 = fused ? Wk : Wq;
    const float* __restrict__ W1 = Wv;    // used only when fused
    float* __restrict__ C0 = fused ? g_K : g_Q;
    float* __restrict__ C1 = g_V;

    const int tid = threadIdx.x;
    const int ty = tid >> 4;          // 0..7  (8 rows each)
    const int tx = tid & 15;          // 0..15 (4 cols each)
    const int bm = blockIdx.y << 6;
    const int bn = blockIdx.x << 6;

    const int ar = tid >> 1;
    const int ac = (tid & 1) << 3;
    const int wr = tid >> 3;
    const int wc = (tid & 7) << 3;

    const float* Ap  = A + (size_t)(bm + ar) * HIN_ + ac;
    const float* W0p = W0 + (size_t)wr * HE_ + bn + wc;
    const float* W1p = W1 + (size_t)wr * HE_ + bn + wc;

    // smem cp.async destinations (per buffer / per mat), 2 x 16B per thread
    uint32_t ws0[2], ws1[2];
    ws0[0] = smem_u32(&Ws[0][0][wr][wc]);
    ws0[1] = smem_u32(&Ws[1][0][wr][wc]);
    ws1[0] = smem_u32(&Ws[0][1][wr][wc]);
    ws1[1] = smem_u32(&Ws[1][1][wr][wc]);

    u64 acc0[8][2], acc1[8][2];
#pragma unroll
    for (int i = 0; i < 8; i++) {
        acc0[i][0] = 0ull; acc0[i][1] = 0ull;
        acc1[i][0] = 0ull; acc1[i][1] = 0ull;
    }

    // swizzle: storage col of (k, m) = m ^ (((k>>2)&3)<<2)
    {   // prologue: chunk 0
        CP_ASYNC16(ws0[0], W0p);
        CP_ASYNC16(ws0[0] + 16, W0p + 4);
        if (fused) {
            CP_ASYNC16(ws1[0], W1p);
            CP_ASYNC16(ws1[0] + 16, W1p + 4);
        }
        CP_COMMIT();
        float4 a0 = *(const float4*)(Ap);
        float4 a1 = *(const float4*)(Ap + 4);
        float av[8] = {a0.x, a0.y, a0.z, a0.w, a1.x, a1.y, a1.z, a1.w};
#pragma unroll
        for (int j = 0; j < 8; j++) {
            int k = ac + j;
            AsT[0][k][ar ^ (((k >> 2) & 3) << 2)] = av[j];
        }
        CP_WAIT0();
    }
    __syncthreads();

    int buf = 0;
    for (int it = 1; it <= 64; it++) {
        float4 a0, a1;
        int nb = buf ^ 1;
        if (it < 64) {   // start W streams + A prefetch for chunk it
            const float* w0s = W0p + (size_t)it * 16 * HE_;
            CP_ASYNC16(ws0[nb], w0s);
            CP_ASYNC16(ws0[nb] + 16, w0s + 4);
            if (fused) {
                const float* w1s = W1p + (size_t)it * 16 * HE_;
                CP_ASYNC16(ws1[nb], w1s);
                CP_ASYNC16(ws1[nb] + 16, w1s + 4);
            }
            CP_COMMIT();
            a0 = *(const float4*)(Ap + it * 16);
            a1 = *(const float4*)(Ap + it * 16 + 4);
        }

        // compute chunk it-1 from buf
#pragma unroll
        for (int kk = 0; kk < 16; kk++) {
            int cx = ((kk >> 2) & 3) << 2;
            float4 aa0 = *(const float4*)&AsT[buf][kk][(ty << 3) ^ cx];
            float4 aa1 = *(const float4*)&AsT[buf][kk][((ty << 3) + 4) ^ cx];
            ulonglong2 w2 =
                *(const ulonglong2*)&Ws[buf][0][kk][tx << 2];  // packed span
            float a[8] = {aa0.x, aa0.y, aa0.z, aa0.w,
                          aa1.x, aa1.y, aa1.z, aa1.w};
#pragma unroll
            for (int i = 0; i < 8; i++) {
                u64 ad = pack2(a[i], a[i]);
                fma2(acc0[i][0], ad, w2.x);
                fma2(acc0[i][1], ad, w2.y);
            }
            if (fused) {
                ulonglong2 v2 =
                    *(const ulonglong2*)&Ws[buf][1][kk][tx << 2];
#pragma unroll
                for (int i = 0; i < 8; i++) {
                    u64 ad = pack2(a[i], a[i]);
                    fma2(acc1[i][0], ad, v2.x);
                    fma2(acc1[i][1], ad, v2.y);
                }
            }
        }

        if (it < 64) {
            float av[8] = {a0.x, a0.y, a0.z, a0.w, a1.x, a1.y, a1.z, a1.w};
#pragma unroll
            for (int j = 0; j < 8; j++) {
                int k = ac + j;
                AsT[nb][k][ar ^ (((k >> 2) & 3) << 2)] = av[j];
            }
            CP_WAIT0();
            __syncthreads();
            buf = nb;
        }
    }

    // Epilogue: Q and K carry the softmax scale; V is unscaled.
#pragma unroll
    for (int i = 0; i < 8; i++) {
        float2 p0 = unpack2(acc0[i][0]);
        float2 p1 = unpack2(acc0[i][1]);
        float4 r = make_float4(p0.x * scale, p0.y * scale,
                               p1.x * scale, p1.y * scale);
        *(float4*)&C0[(size_t)(bm + (ty << 3) + i) * HE_ + bn + (tx << 2)] = r;
    }
    if (fused) {
#pragma unroll
        for (int i = 0; i < 8; i++) {
            float2 p0 = unpack2(acc1[i][0]);
            float2 p1 = unpack2(acc1[i][1]);
            float4 r = make_float4(p0.x, p0.y, p1.x, p1.y);
            *(float4*)&C1[(size_t)(bm + (ty << 3) + i) * HE_ + bn + (tx << 2)] = r;
        }
    }
}

// ---------------------------------------------------------------------------
// Flash attention, split-K. R17: QK uses row-pair-packed accumulators
// (q-pairs read free as u64 from transposed QsT; K broadcast-packed 4x/e).
// Softmax, P store (KsT plain reuse), and PV are exactly the R15 versions.
// ---------------------------------------------------------------------------
__global__ __launch_bounds__(128) void flash_attn_split() {
    __shared__ __align__(16) float QsT[64][64];  // swizzled [e][qrow]
    __shared__ __align__(16) float KsT[64][64];  // swizzled [e][krow]; P reuse
    __shared__ __align__(16) float Vs[64][64];   // [krow][e]

    const int tid = threadIdx.x;
    const int ty = tid >> 4;
    const int tx = tid & 15;
    const int q0 = blockIdx.x << 6;
    const int h  = blockIdx.y;
    const int b  = blockIdx.z >> 1;
    const int sp = blockIdx.z & 1;

    const size_t baseQ  = ((size_t)(b * T_ + q0) * H_ + h) * E_;
    const size_t baseKV = ((size_t)(b * T_ + sp * TSPLIT) * H_ + h) * E_;

    for (int idx = tid; idx < 1024; idx += 128) {
        int row = idx >> 4;
        int t = idx & 15;
        int c = t << 2;
        float4 v = *(const float4*)(g_Q + baseQ + (size_t)row * HE_ + c);
        int col = (((row >> 2) ^ t) << 2) | (row & 3);
        QsT[c + 0][col] = v.x;
        QsT[c + 1][col] = v.y;
        QsT[c + 2][col] = v.z;
        QsT[c + 3][col] = v.w;
    }

    float m[8], l[8];
    u64 o2[8][2];
#pragma unroll
    for (int i = 0; i < 8; i++) {
        m[i] = -1e30f;
        l[i] = 0.f;
        o2[i][0] = 0ull;
        o2[i][1] = 0ull;
    }

    for (int k0 = 0; k0 < TSPLIT; k0 += 64) {
        __syncthreads();
        for (int idx = tid; idx < 1024; idx += 128) {
            int row = idx >> 4;
            int t = idx & 15;
            int c = t << 2;
            size_t g = baseKV + (size_t)(k0 + row) * HE_ + c;
            float4 kv = *(const float4*)(g_K + g);
            int col = (((row >> 2) ^ t) << 2) | (row & 3);
            KsT[c + 0][col] = kv.x;
            KsT[c + 1][col] = kv.y;
            KsT[c + 2][col] = kv.z;
            KsT[c + 3][col] = kv.w;
            *(float4*)&Vs[row][c] = *(const float4*)(g_V + g);
        }
        __syncthreads();

        // S = Q K^T: row-pair accumulators s2[pair][col]; K broadcast-packed.
        // Pair p = local rows (2p, 2p+1); identical per-element fma order
        // to the row-major version -> bit-identical results.
        u64 s2[4][4];
#pragma unroll
        for (int p = 0; p < 4; p++)
#pragma unroll
            for (int j = 0; j < 4; j++) s2[p][j] = 0ull;
#pragma unroll 4
        for (int x = 0; x < 16; x++) {
#pragma unroll
            for (int ee = 0; ee < 4; ee++) {
                int e = (x << 2) + ee;
                ulonglong2 qa =
                    *(const ulonglong2*)&QsT[e][((2 * ty) ^ x) << 2];
                ulonglong2 qb =
                    *(const ulonglong2*)&QsT[e][((2 * ty + 1) ^ x) << 2];
                float4 k4 = *(const float4*)&KsT[e][(tx ^ x) << 2];
                u64 kd0 = pack2(k4.x, k4.x);
                u64 kd1 = pack2(k4.y, k4.y);
                u64 kd2 = pack2(k4.z, k4.z);
                u64 kd3 = pack2(k4.w, k4.w);
                u64 q64[4] = {qa.x, qa.y, qb.x, qb.y};
#pragma unroll
                for (int p = 0; p < 4; p++) {
                    fma2(s2[p][0], q64[p], kd0);
                    fma2(s2[p][1], q64[p], kd1);
                    fma2(s2[p][2], q64[p], kd2);
                    fma2(s2[p][3], q64[p], kd3);
                }
            }
        }

        // Unpack pair-major accumulators to per-row s[8][4]
        float s[8][4];
#pragma unroll
        for (int p = 0; p < 4; p++)
#pragma unroll
            for (int j = 0; j < 4; j++) {
                float2 t2 = unpack2(s2[p][j]);
                s[2 * p][j] = t2.x;
                s[2 * p + 1][j] = t2.y;
            }

        // Online softmax (exact R15 version)
#pragma unroll
        for (int i = 0; i < 8; i++) {
            float mx = fmaxf(fmaxf(s[i][0], s[i][1]), fmaxf(s[i][2], s[i][3]));
#pragma unroll
            for (int off = 8; off >= 1; off >>= 1)
                mx = fmaxf(mx, __shfl_xor_sync(0xffffffffu, mx, off));
            float mnew = fmaxf(m[i], mx);
            float corr = __expf(m[i] - mnew);
            float rs = 0.f;
#pragma unroll
            for (int j = 0; j < 4; j++) {
                s[i][j] = __expf(s[i][j] - mnew);
                rs += s[i][j];
            }
#pragma unroll
            for (int off = 8; off >= 1; off >>= 1)
                rs += __shfl_xor_sync(0xffffffffu, rs, off);
            l[i] = l[i] * corr + rs;
            m[i] = mnew;
            u64 cd = pack2(corr, corr);
            o2[i][0] = mul2(o2[i][0], cd);
            o2[i][1] = mul2(o2[i][1], cd);
        }

        __syncthreads();   // all warps done reading KsT as K
#pragma unroll
        for (int i = 0; i < 8; i++)
            *(float4*)&KsT[(ty << 3) + i][tx << 2] =
                make_float4(s[i][0], s[i][1], s[i][2], s[i][3]);
        __syncthreads();   // P visible (plain layout)

        // O += P @ V (exact R15 version)
#pragma unroll 4
        for (int k = 0; k < 64; k += 4) {
            ulonglong2 vp[4];
#pragma unroll
            for (int kk = 0; kk < 4; kk++)
                vp[kk] = *(const ulonglong2*)&Vs[k + kk][tx << 2];
#pragma unroll
            for (int i = 0; i < 8; i++) {
                float4 p4 = *(const float4*)&KsT[(ty << 3) + i][k];
                float p[4] = {p4.x, p4.y, p4.z, p4.w};
#pragma unroll
                for (int kk = 0; kk < 4; kk++) {
                    u64 pd = pack2(p[kk], p[kk]);
                    fma2(o2[i][0], pd, vp[kk].x);
                    fma2(o2[i][1], pd, vp[kk].y);
                }
            }
        }
    }

    const size_t opBase = (size_t)sp * BT_ * HE_;
    const size_t mlBase = (size_t)sp * BT_ * H_;
#pragma unroll
    for (int i = 0; i < 8; i++) {
        int row = q0 + (ty << 3) + i;
        float2 p0 = unpack2(o2[i][0]);
        float2 p1 = unpack2(o2[i][1]);
        *(float4*)&g_Op[opBase + ((size_t)(b * T_ + row) * H_ + h) * E_ +
                        (tx << 2)] = make_float4(p0.x, p0.y, p1.x, p1.y);
        if (tx == 0) {
            size_t mi = mlBase + (size_t)(b * T_ + row) * H_ + h;
            g_m[mi] = m[i];
            g_l[mi] = l[i];
        }
    }
}

// ---------------------------------------------------------------------------
// Combine (unchanged).
// ---------------------------------------------------------------------------
__global__ __launch_bounds__(256) void flash_combine(float* __restrict__ Out) {
    int idx = blockIdx.x * 256 + threadIdx.x;   // float4 index
    int rowh = idx >> 4;                         // (b*T+t)*H + h
    float m0 = g_m[rowh];
    float m1 = g_m[BT_ * H_ + rowh];
    float l0 = g_l[rowh];
    float l1 = g_l[BT_ * H_ + rowh];
    float M = fmaxf(m0, m1);
    float w0 = __expf(m0 - M);
    float w1 = __expf(m1 - M);
    float inv = 1.0f / (l0 * w0 + l1 * w1);

    const float4* Op4 = (const float4*)g_Op;
    float4 o0 = Op4[idx];
    float4 o1 = Op4[(BT_ * HE_ / 4) + idx];
    float4 r;
    r.x = (o0.x * w0 + o1.x * w1) * inv;
    r.y = (o0.y * w0 + o1.y * w1) * inv;
    r.z = (o0.z * w0 + o1.z * w1) * inv;
    r.w = (o0.w * w0 + o1.w * w1) * inv;
    ((float4*)Out)[idx] = r;
}

// ---------------------------------------------------------------------------
extern "C" void kernel_launch(void* const* d_in, const int* in_sizes, int n_in,
                              void* d_out, int out_size) {
    const float* query     = (const float*)d_in[0];
    const float* key_value = (const float*)d_in[1];
    const float* Wq        = (const float*)d_in[2];
    const float* Wk        = (const float*)d_in[3];
    const float* Wv        = (const float*)d_in[4];
    float* out = (float*)d_out;

    const float scale = 0.35355339059327379f;  // 64^(-1/4)

    dim3 gproj(HE_ / 64, BT_ / 64, 2);         // (16, 128, 2): z0=Q, z1=K+V
    proj_gemm<<<gproj, 128>>>(query, key_value, Wq, Wk, Wv, scale);

    dim3 gattn(T_ / 64, H_, B_ * NSPLIT);      // (32, 16, 8)
    flash_attn_split<<<gattn, 128>>>();

    flash_combine<<<BT_ * HE_ / 4 / 256, 256>>>(out);
}